// round 1
// baseline (speedup 1.0000x reference)
#include <cuda_runtime.h>

#define ATT_H 128
#define KVH   256
#define NB    2
#define NS    1024
#define NQ    512

// scratch (no allocations allowed)
__device__ float g_proj_kv[NB*NS*ATT_H];   // (B*S, 128)
__device__ float g_proj_q [NB*NQ*ATT_H];   // (B*SQ, 128)
__device__ float g_E      [NB*NQ*NS];      // unnormalized exp(score)

__device__ __forceinline__ float fast_tanh(float x){ float y; asm("tanh.approx.f32 %0, %1;" : "=f"(y) : "f"(x)); return y; }
__device__ __forceinline__ float fast_ex2 (float x){ float y; asm("ex2.approx.f32 %0, %1;"  : "=f"(y) : "f"(x)); return y; }

// ---------------- Kernel 1: proj_kv = kv@W_kv+b_kv ; proj_q = q@W_q+b_q ----------------
// 16 rows per block. blocks [0,128): kv rows, [128,192): q rows.
__global__ void __launch_bounds__(256) proj_kernel(
    const float* __restrict__ kv, const float* __restrict__ qy,
    const float* __restrict__ Wkv, const float* __restrict__ bkv,
    const float* __restrict__ Wq,  const float* __restrict__ bq)
{
    __shared__ float in_sh[16*256];     // 16KB
    __shared__ float w_sh [64*128];     // 32KB (k-chunk of 64)
    const int tid = threadIdx.x;
    const int rb  = blockIdx.x;

    const float *in, *W, *bias; float* out; int row0;
    if (rb < 128) { in = kv; W = Wkv; bias = bkv; out = g_proj_kv; row0 = rb*16; }
    else          { in = qy; W = Wq;  bias = bq;  out = g_proj_q;  row0 = (rb-128)*16; }

    // load input tile 16x256 (coalesced float4)
    const float4* insrc = (const float4*)(in + row0*256);
    float4* ish4 = (float4*)in_sh;
    #pragma unroll
    for (int i = 0; i < 4; i++) ish4[tid + 256*i] = insrc[tid + 256*i];

    const int a4 = tid & 31;   // float4 column group (a = a4*4..a4*4+3)
    const int rg = tid >> 5;   // 0..7 -> rows rg*2, rg*2+1
    float4 acc0 = make_float4(0.f,0.f,0.f,0.f);
    float4 acc1 = make_float4(0.f,0.f,0.f,0.f);

    for (int kc = 0; kc < 4; kc++) {
        __syncthreads();
        const float4* wsrc = (const float4*)(W + kc*64*128);
        float4* wsh4 = (float4*)w_sh;
        #pragma unroll
        for (int i = 0; i < 8; i++) wsh4[tid + 256*i] = wsrc[tid + 256*i];
        __syncthreads();

        const float* i0p = in_sh + (rg*2    )*256 + kc*64;
        const float* i1p = in_sh + (rg*2 + 1)*256 + kc*64;
        #pragma unroll 8
        for (int k = 0; k < 64; k++) {
            float4 w = ((const float4*)w_sh)[k*32 + a4];
            float i0 = i0p[k], i1 = i1p[k];
            acc0.x += i0*w.x; acc0.y += i0*w.y; acc0.z += i0*w.z; acc0.w += i0*w.w;
            acc1.x += i1*w.x; acc1.y += i1*w.y; acc1.z += i1*w.z; acc1.w += i1*w.w;
        }
    }
    float4 bb = ((const float4*)bias)[a4];
    acc0.x += bb.x; acc0.y += bb.y; acc0.z += bb.z; acc0.w += bb.w;
    acc1.x += bb.x; acc1.y += bb.y; acc1.z += bb.z; acc1.w += bb.w;
    ((float4*)(out + (row0 + rg*2    )*ATT_H))[a4] = acc0;
    ((float4*)(out + (row0 + rg*2 + 1)*ATT_H))[a4] = acc1;
}

// ---------------- Kernel 2: E[b,q,s] = exp( sum_a w_v[a]*tanh(pk[s,a]+pq[q,a]) + b_v ) ----------------
// Tile: 8 q x 64 s per block. 2048 blocks. MUFU(tanh)-bound by design.
__global__ void __launch_bounds__(256) score_kernel(
    const float* __restrict__ wv_g, const float* __restrict__ bv_g)
{
    __shared__ float4 pk_sh[64*33];   // 64 s-rows, 32 float4 + 1 pad -> conflict-free
    __shared__ float4 pq_sh[8*32];    // 8 q-rows x 128 floats
    __shared__ float4 wv_sh[32];

    const int tid = threadIdx.x;
    const int bid = blockIdx.x;       // 2048 = 128 q-tiles * 16 s-tiles
    const int st  = bid & 15;
    const int qt  = bid >> 4;         // 0..127
    const int b   = qt >> 6;
    const int q0  = (qt & 63) * 8;
    const int s0  = st * 64;

    const float4* pqsrc = (const float4*)(g_proj_q + (b*NQ + q0)*ATT_H);
    pq_sh[tid] = pqsrc[tid];                       // 256 float4 exactly
    if (tid < 32) wv_sh[tid] = ((const float4*)wv_g)[tid];
    const float4* pksrc = (const float4*)(g_proj_kv + (b*NS + s0)*ATT_H);
    #pragma unroll
    for (int i = 0; i < 8; i++) {
        int f4 = tid + 256*i;                      // 0..2047
        pk_sh[(f4 >> 5)*33 + (f4 & 31)] = pksrc[f4];
    }
    __syncthreads();

    const float bv = __ldg(bv_g);
    const int sl = tid & 63;          // s within tile (warp lanes consecutive)
    const int qq = tid >> 6;          // 0..3 -> q pair {2qq, 2qq+1}

    float acc0 = 0.f, acc1 = 0.f;
    const float4* pkp  = pk_sh + sl*33;
    const float4* pq0p = pq_sh + (2*qq    )*32;
    const float4* pq1p = pq_sh + (2*qq + 1)*32;

    #pragma unroll 8
    for (int a4 = 0; a4 < 32; a4++) {
        float4 pk = pkp[a4];
        float4 w  = wv_sh[a4];
        float4 p0 = pq0p[a4];
        float4 p1 = pq1p[a4];
        acc0 += w.x * fast_tanh(pk.x + p0.x);
        acc0 += w.y * fast_tanh(pk.y + p0.y);
        acc0 += w.z * fast_tanh(pk.z + p0.z);
        acc0 += w.w * fast_tanh(pk.w + p0.w);
        acc1 += w.x * fast_tanh(pk.x + p1.x);
        acc1 += w.y * fast_tanh(pk.y + p1.y);
        acc1 += w.z * fast_tanh(pk.z + p1.z);
        acc1 += w.w * fast_tanh(pk.w + p1.w);
    }
    // scores bounded by sum|w_v|+|b_v| <= ~11.4 -> exp safe without max-subtraction
    float* Eout = g_E + (size_t)(b*NQ + q0 + 2*qq)*NS + s0 + sl;
    Eout[0]  = fast_ex2((acc0 + bv) * 1.44269504f);
    Eout[NS] = fast_ex2((acc1 + bv) * 1.44269504f);
}

// ---------------- Kernel 3: row-sum, normalize weights, output GEMM ----------------
// Tile: 8 q x 128 h-half per block. 256 blocks. Deterministic (no atomics).
__global__ void __launch_bounds__(256) out_kernel(
    const float* __restrict__ kv, float* __restrict__ out_o, float* __restrict__ out_w)
{
    __shared__ float E_sh[8*1024];    // 32KB
    __shared__ float inv_sh[8];

    const int tid = threadIdx.x;
    const int bid = blockIdx.x;       // 256 = 128 q-tiles * 2 h-halves
    const int hh  = bid & 1;
    const int qt  = bid >> 1;
    const int b   = qt >> 6;
    const int q0  = (qt & 63) * 8;

    const float4* Esrc = (const float4*)(g_E + (size_t)(b*NQ + q0)*NS);
    float4* Esh4 = (float4*)E_sh;
    #pragma unroll
    for (int i = 0; i < 8; i++) Esh4[tid + 256*i] = Esrc[tid + 256*i];
    __syncthreads();

    // per-q row sums (warp w handles q=w)
    {
        const int w = tid >> 5, lane = tid & 31;
        const float4* row = (const float4*)(E_sh + w*1024);
        float s = 0.f;
        #pragma unroll
        for (int i = 0; i < 8; i++) { float4 v = row[lane + 32*i]; s += (v.x + v.y) + (v.z + v.w); }
        #pragma unroll
        for (int o = 16; o > 0; o >>= 1) s += __shfl_xor_sync(0xffffffffu, s, o);
        if (lane == 0) inv_sh[w] = 1.0f / s;
    }
    __syncthreads();

    // normalized attention weights (write once, from hh==0 blocks)
    if (hh == 0) {
        float4* Wdst = (float4*)(out_w + (size_t)(b*NQ + q0)*NS);
        #pragma unroll
        for (int i = 0; i < 8; i++) {
            int f4 = tid + 256*i;
            float inv = inv_sh[f4 >> 8];     // f4/256 = q index
            float4 v = Esh4[f4];
            v.x *= inv; v.y *= inv; v.z *= inv; v.w *= inv;
            Wdst[f4] = v;
        }
    }

    // out[b,q,h] = (sum_s E[q,s] * kv[b,s,h]) * inv[q]
    const int hloc = tid & 127;
    const int qg   = tid >> 7;        // 0/1 -> q = qg*4 + j
    const float* kvp = kv + (size_t)b*NS*KVH + hh*128 + hloc;
    float acc[4] = {0.f, 0.f, 0.f, 0.f};
    const float4* E0 = (const float4*)(E_sh + (qg*4)*1024);

    #pragma unroll 4
    for (int s4 = 0; s4 < 256; s4++) {
        float4 e0 = E0[s4], e1 = E0[256 + s4], e2 = E0[512 + s4], e3 = E0[768 + s4];
        float k0 = kvp[(s4*4 + 0)*KVH];
        float k1 = kvp[(s4*4 + 1)*KVH];
        float k2 = kvp[(s4*4 + 2)*KVH];
        float k3 = kvp[(s4*4 + 3)*KVH];
        acc[0] += e0.x*k0; acc[0] += e0.y*k1; acc[0] += e0.z*k2; acc[0] += e0.w*k3;
        acc[1] += e1.x*k0; acc[1] += e1.y*k1; acc[1] += e1.z*k2; acc[1] += e1.w*k3;
        acc[2] += e2.x*k0; acc[2] += e2.y*k1; acc[2] += e2.z*k2; acc[2] += e2.w*k3;
        acc[3] += e3.x*k0; acc[3] += e3.y*k1; acc[3] += e3.z*k2; acc[3] += e3.w*k3;
    }
    float* od = out_o + (size_t)(b*NQ + q0 + qg*4)*KVH + hh*128 + hloc;
    #pragma unroll
    for (int j = 0; j < 4; j++) od[j*KVH] = acc[j] * inv_sh[qg*4 + j];
}

extern "C" void kernel_launch(void* const* d_in, const int* in_sizes, int n_in,
                              void* d_out, int out_size)
{
    const float* kv  = (const float*)d_in[0];   // (2,1024,256)
    const float* qy  = (const float*)d_in[1];   // (2,512,256)
    const float* Wkv = (const float*)d_in[2];   // (256,128)
    const float* bkv = (const float*)d_in[3];   // (128)
    const float* Wq  = (const float*)d_in[4];   // (256,128)
    const float* bq  = (const float*)d_in[5];   // (128)
    const float* wv  = (const float*)d_in[6];   // (128)
    const float* bv  = (const float*)d_in[7];   // scalar

    float* out_o = (float*)d_out;               // attention_output: 2*512*256
    float* out_w = out_o + NB*NQ*KVH;           // attention_weight: 2*512*1024

    proj_kernel <<<192,  256>>>(kv, qy, Wkv, bkv, Wq, bq);
    score_kernel<<<2048, 256>>>(wv, bv);
    out_kernel  <<<256,  256>>>(kv, out_o, out_w);
}